// round 13
// baseline (speedup 1.0000x reference)
#include <cuda_runtime.h>

#define N_NODES 50000
#define N_EDGES 800000
#define IN_C    64
#define HID_C   128
#define OUT_C   64

// ---------------- scratch (static device globals; no allocation) ----------------
__device__ __align__(16) float g_S1 [N_NODES * IN_C];   // layer-1 aggregate (incl self)
__device__ __align__(16) float g_P  [N_NODES * OUT_C];  // H·W2_j  (message proj)
__device__ __align__(16) float g_Q  [N_NODES * OUT_C];  // H·W2_i  (self proj)
__device__ __align__(16) float g_S2p[N_NODES * OUT_C];  // layer-2 proj-aggregate
__device__ __align__(16) float g_cnt[N_NODES];          // in-degree (float)
__device__ __align__(16) float g_sea[N_NODES];          // scatter-sum of edge_attr
__device__ __align__(16) int   g_idx[2 * N_EDGES];      // [src(E), dst(E)] as int32
__device__ int g_is64;                                  // edge_index dtype flag

// ---------------- helpers ----------------
__device__ __forceinline__ void red_add_v4(float* p, float4 v) {
    asm volatile("red.global.add.v4.f32 [%0], {%1,%2,%3,%4};"
                 :: "l"(p), "f"(v.x), "f"(v.y), "f"(v.z), "f"(v.w) : "memory");
}

// ---------------- dtype detect (1 warp, parallel) ----------------
__global__ void detect_kernel(const int* __restrict__ ei32) {
    int lane = threadIdx.x & 31;
    int acc = 0;
#pragma unroll
    for (int j = 0; j < 4; j++) acc |= ei32[2 * (lane + 32 * j) + 1];
#pragma unroll
    for (int off = 16; off; off >>= 1) acc |= __shfl_xor_sync(0xffffffffu, acc, off);
    if (lane == 0) g_is64 = (acc == 0) ? 1 : 0;
}

// ---------------- fused: index convert + S1 = x + cnt/sea = 0 -------------------
__global__ void convert_init_kernel(const void* __restrict__ ei,
                                    const float* __restrict__ x) {
    int i = blockIdx.x * blockDim.x + threadIdx.x;
    if (i < 2 * N_EDGES) {
        int v;
        if (g_is64) v = (int)((const long long*)ei)[i];
        else        v = ((const int*)ei)[i];
        g_idx[i] = v;
    }
    if (i < N_NODES * IN_C) g_S1[i] = x[i];
    if (i < N_NODES) { g_cnt[i] = 0.0f; g_sea[i] = 0.0f; }
}

// ---------------- edge gather/scatter: S[dst] += feat[src] (C=64 both layers) ----
template <bool STATS>
__device__ __forceinline__ void scatter_body(const float* __restrict__ feat,
                                             float* __restrict__ S,
                                             const float* __restrict__ ea) {
    const int CH = 16;  // 64 floats / 4
    long long t = (long long)blockIdx.x * blockDim.x + threadIdx.x;
    if (t >= (long long)N_EDGES * CH) return;
    int e = (int)(t / CH);
    int c = (int)(t % CH);
    int s = __ldg(&g_idx[e]);
    int d = __ldg(&g_idx[N_EDGES + e]);
    if (STATS && c == 0) {
        atomicAdd(&g_cnt[d], 1.0f);
        atomicAdd(&g_sea[d], ea[e]);
    }
    float4 v = reinterpret_cast<const float4*>(feat)[(long long)s * CH + c];
    red_add_v4(reinterpret_cast<float*>(
                   &reinterpret_cast<float4*>(S)[(long long)d * CH + c]), v);
}

__global__ void scatter1_kernel(const float* __restrict__ x,
                                const float* __restrict__ ea) {
    scatter_body<true>(x, g_S1, ea);
}
__global__ void scatter2_kernel() {
    scatter_body<false>(g_P, g_S2p, nullptr);
}

// ---------------- node1: 2-D register-tiled GEMMs with broadcast smem reads ------
// Stage A: H[16 nodes][128] = relu(cnt*(x·W1_i + b1) + S1·W1_j + sea*w1e)
//   thread tile 4n x 4o; xsT/ssT stored k-major so smem reads are warp-broadcast.
// Stage B: Q = H·W2_i, P = H·W2_j, thread tile 4n x 2o over k=128; H k-major.
#define HST 20   // hsT row stride (floats): 80B, keeps float4 alignment
__global__ void __launch_bounds__(128) node1_kernel(const float* __restrict__ x,
                                                    const float* __restrict__ W1,
                                                    const float* __restrict__ b1,
                                                    const float* __restrict__ W2) {
    __shared__ float xsT[IN_C][16];       // [k][n]
    __shared__ float ssT[IN_C][16];
    __shared__ float hsT[HID_C][HST];     // [k][n] padded
    __shared__ float cs[16], es[16];
    int node0 = blockIdx.x * 16;
    int tid = threadIdx.x;

    // transpose-load x and S1 tiles: thread handles 2 (node, k4) chunks
    for (int idx = tid; idx < 16 * (IN_C / 4); idx += 128) {
        int n = idx / (IN_C / 4);
        int k4 = idx % (IN_C / 4);
        float4 xv = reinterpret_cast<const float4*>(x)[(long long)(node0 + n) * (IN_C / 4) + k4];
        float4 sv = reinterpret_cast<const float4*>(g_S1)[(long long)(node0 + n) * (IN_C / 4) + k4];
        int k = k4 * 4;
        xsT[k + 0][n] = xv.x; xsT[k + 1][n] = xv.y; xsT[k + 2][n] = xv.z; xsT[k + 3][n] = xv.w;
        ssT[k + 0][n] = sv.x; ssT[k + 1][n] = sv.y; ssT[k + 2][n] = sv.z; ssT[k + 3][n] = sv.w;
    }
    if (tid < 16) {
        cs[tid] = g_cnt[node0 + tid] + 1.0f;
        es[tid] = g_sea[node0 + tid];
    }
    __syncthreads();

    int og = tid & 31;        // o-group: same for all lanes' n? no: lane = og
    int ng = tid >> 5;        // warp id = node group (all lanes share it -> broadcast)
    int n0 = ng * 4;

    // ---- Stage A: 4n x 4o per thread, o0 = og*4 (covers 128 outputs) ----
    {
        int o0 = og * 4;
        float ax[4][4], as_[4][4];
#pragma unroll
        for (int i = 0; i < 4; i++)
#pragma unroll
            for (int j = 0; j < 4; j++) { ax[i][j] = 0.0f; as_[i][j] = 0.0f; }

#pragma unroll 4
        for (int k = 0; k < IN_C; k++) {
            float4 xv = *reinterpret_cast<const float4*>(&xsT[k][n0]);  // broadcast
            float4 sv = *reinterpret_cast<const float4*>(&ssT[k][n0]);  // broadcast
            float4 wx = *reinterpret_cast<const float4*>(&W1[k * HID_C + o0]);
            float4 ws = *reinterpret_cast<const float4*>(&W1[(IN_C + k) * HID_C + o0]);
            const float xa[4] = {xv.x, xv.y, xv.z, xv.w};
            const float sa[4] = {sv.x, sv.y, sv.z, sv.w};
            const float wxa[4] = {wx.x, wx.y, wx.z, wx.w};
            const float wsa[4] = {ws.x, ws.y, ws.z, ws.w};
#pragma unroll
            for (int i = 0; i < 4; i++)
#pragma unroll
                for (int j = 0; j < 4; j++) {
                    ax[i][j] += xa[i] * wxa[j];
                    as_[i][j] += sa[i] * wsa[j];
                }
        }
        float4 bo = *reinterpret_cast<const float4*>(&b1[o0]);
        float4 we = *reinterpret_cast<const float4*>(&W1[2 * IN_C * HID_C + o0]);
        const float boa[4] = {bo.x, bo.y, bo.z, bo.w};
        const float wea[4] = {we.x, we.y, we.z, we.w};
#pragma unroll
        for (int i = 0; i < 4; i++) {
            float c = cs[n0 + i], e = es[n0 + i];
#pragma unroll
            for (int j = 0; j < 4; j++) {
                float v = c * (ax[i][j] + boa[j]) + as_[i][j] + e * wea[j];
                hsT[o0 + j][n0 + i] = fmaxf(v, 0.0f);
            }
        }
    }
    __syncthreads();

    // ---- Stage B: 4n x 2o per thread over k=128, o2 = og*2 (covers 64 outputs) --
    {
        int o2 = og * 2;
        float q[4][2], p[4][2];
#pragma unroll
        for (int i = 0; i < 4; i++)
#pragma unroll
            for (int j = 0; j < 2; j++) { q[i][j] = 0.0f; p[i][j] = 0.0f; }

#pragma unroll 4
        for (int k = 0; k < HID_C; k++) {
            float4 hv = *reinterpret_cast<const float4*>(&hsT[k][n0]);  // broadcast
            float2 wi = *reinterpret_cast<const float2*>(&W2[k * OUT_C + o2]);
            float2 wj = *reinterpret_cast<const float2*>(&W2[(HID_C + k) * OUT_C + o2]);
            const float ha[4] = {hv.x, hv.y, hv.z, hv.w};
#pragma unroll
            for (int i = 0; i < 4; i++) {
                q[i][0] += ha[i] * wi.x;
                q[i][1] += ha[i] * wi.y;
                p[i][0] += ha[i] * wj.x;
                p[i][1] += ha[i] * wj.y;
            }
        }
#pragma unroll
        for (int i = 0; i < 4; i++) {
            long long base = (long long)(node0 + n0 + i) * OUT_C + o2;
            *reinterpret_cast<float2*>(&g_Q[base])   = make_float2(q[i][0], q[i][1]);
            *reinterpret_cast<float2*>(&g_P[base])   = make_float2(p[i][0], p[i][1]);
            *reinterpret_cast<float2*>(&g_S2p[base]) = make_float2(p[i][0], p[i][1]);
        }
    }
}

// ---------------- final: layer-2 elementwise epilogue + log_softmax -------------
__global__ void __launch_bounds__(256) final_kernel(const float* __restrict__ W2,
                                                    const float* __restrict__ b2,
                                                    float* __restrict__ out) {
    int warp = (blockIdx.x * blockDim.x + threadIdx.x) >> 5;
    int lane = threadIdx.x & 31;
    if (warp >= N_NODES) return;
    int v = warp;
    float cnt1 = g_cnt[v] + 1.0f;
    float sea  = g_sea[v];
    long long base = (long long)v * OUT_C;
    const float* w2e = &W2[2 * HID_C * OUT_C];

    float v0 = fmaxf(cnt1 * (g_Q[base + lane]      + b2[lane])      + g_S2p[base + lane]      + sea * w2e[lane],      0.0f);
    float v1 = fmaxf(cnt1 * (g_Q[base + lane + 32] + b2[lane + 32]) + g_S2p[base + lane + 32] + sea * w2e[lane + 32], 0.0f);

    float m = fmaxf(v0, v1);
#pragma unroll
    for (int off = 16; off; off >>= 1) m = fmaxf(m, __shfl_xor_sync(0xffffffffu, m, off));
    float s = __expf(v0 - m) + __expf(v1 - m);
#pragma unroll
    for (int off = 16; off; off >>= 1) s += __shfl_xor_sync(0xffffffffu, s, off);
    float ls = logf(s) + m;
    out[base + lane]      = v0 - ls;
    out[base + lane + 32] = v1 - ls;
}

// ---------------- launch ----------------
extern "C" void kernel_launch(void* const* d_in, const int* in_sizes, int n_in,
                              void* d_out, int out_size) {
    const float* x  = (const float*)d_in[0];
    const void*  ei = d_in[1];
    const float* ea = (const float*)d_in[2];
    const float* W1 = (const float*)d_in[3];
    const float* b1 = (const float*)d_in[4];
    const float* W2 = (const float*)d_in[5];
    const float* b2 = (const float*)d_in[6];
    for (int i = 0; i < n_in; i++) {
        switch (in_sizes[i]) {
            case N_NODES * IN_C:          x  = (const float*)d_in[i]; break;
            case 2 * N_EDGES:             ei = d_in[i];               break;
            case N_EDGES:                 ea = (const float*)d_in[i]; break;
            case (2 * IN_C + 1) * HID_C:  W1 = (const float*)d_in[i]; break;
            case HID_C:                   b1 = (const float*)d_in[i]; break;
            case (2 * HID_C + 1) * OUT_C: W2 = (const float*)d_in[i]; break;
            case OUT_C:                   b2 = (const float*)d_in[i]; break;
            default: break;
        }
    }
    float* out = (float*)d_out;

    // 0) dtype detect (parallel); fused convert + init
    detect_kernel<<<1, 32>>>((const int*)ei);
    convert_init_kernel<<<(N_NODES * IN_C + 255) / 256, 256>>>(ei, x);
    // 1) layer-1 neighbor gather/scatter (+ fused degree/edge_attr stats)
    {
        long long work = (long long)N_EDGES * (IN_C / 4);
        scatter1_kernel<<<(unsigned)((work + 255) / 256), 256>>>(x, ea);
    }
    // 2) layer-1 linear + relu (H in smem) + W2 projections -> Q, P, S2p seed
    node1_kernel<<<N_NODES / 16, 128>>>(x, W1, b1, W2);
    // 3) layer-2 projected gather/scatter: S2p[dst] += P[src]   (64-wide)
    {
        long long work = (long long)N_EDGES * (OUT_C / 4);
        scatter2_kernel<<<(unsigned)((work + 255) / 256), 256>>>();
    }
    // 4) layer-2 elementwise epilogue + log_softmax
    final_kernel<<<(N_NODES * 32 + 255) / 256, 256>>>(W2, b2, out);
}